// round 11
// baseline (speedup 1.0000x reference)
#include <cuda_runtime.h>
#include <cstdint>

// CenterLoss: mean_i ||x[i] - centers[labels[i]]||^2
// B=16384, C=4000, D=512
// Inputs: x [B*D] f32, labels [B] int32, centers [C*D] f32. Output: scalar f32.
//
// Path-split design: x (32MB, sequential) rides the TMA pipe into smem;
// centers (8MB, gathered) ride the LSU/LDG path into registers. The two
// load paths run concurrently instead of pushing all 40MB through one.

#define B_ROWS 16384
#define C_ROWS 4000
#define THREADS 256
#define BLOCKS  512
#define ROWS_PER_BLOCK 32
#define STAGE_ROWS 8
#define NSTAGES 4                       // 4 stages cover all 32 rows, no refill
#define ROW_BYTES 2048
#define STAGE_BYTES (STAGE_ROWS * ROW_BYTES)   // 16384

// dynamic smem: [0,32) 4 mbarriers ; [1024, 1024+64K) x stages
#define SMEM_MBAR 0
#define SMEM_X    1024
#define SMEM_TOTAL (SMEM_X + NSTAGES * STAGE_BYTES)   // 66560

__device__ __forceinline__ uint32_t smem_u32(const void* p) {
    uint32_t a;
    asm("{ .reg .u64 t; cvta.to.shared.u64 t, %1; cvt.u32.u64 %0, t; }"
        : "=r"(a) : "l"(p));
    return a;
}
__device__ __forceinline__ void mbar_init(uint32_t mbar, uint32_t count) {
    asm volatile("mbarrier.init.shared.b64 [%0], %1;" :: "r"(mbar), "r"(count) : "memory");
}
__device__ __forceinline__ void mbar_expect_tx(uint32_t mbar, uint32_t bytes) {
    asm volatile("mbarrier.arrive.expect_tx.shared.b64 _, [%0], %1;"
                 :: "r"(mbar), "r"(bytes) : "memory");
}
__device__ __forceinline__ void mbar_wait0(uint32_t mbar) {
    uint32_t done;
    asm volatile(
        "{\n\t.reg .pred p;\n\t"
        "mbarrier.try_wait.parity.acquire.cta.shared::cta.b64 p, [%1], 0;\n\t"
        "selp.b32 %0, 1, 0, p;\n\t}"
        : "=r"(done) : "r"(mbar) : "memory");
    while (!done) {
        asm volatile(
            "{\n\t.reg .pred p;\n\t"
            "mbarrier.try_wait.parity.acquire.cta.shared::cta.b64 p, [%1], 0, 0x989680;\n\t"
            "selp.b32 %0, 1, 0, p;\n\t}"
            : "=r"(done) : "r"(mbar) : "memory");
    }
}
__device__ __forceinline__ void bulk_copy(uint32_t dst, const void* src,
                                          uint32_t bytes, uint32_t mbar) {
    asm volatile(
        "cp.async.bulk.shared::cta.global.mbarrier::complete_tx::bytes "
        "[%0], [%1], %2, [%3];"
        :: "r"(dst), "l"(src), "r"(bytes), "r"(mbar) : "memory");
}

__global__ __launch_bounds__(THREADS)
void center_loss_kernel(const float* __restrict__ x,
                        const int* __restrict__ labels,
                        const float* __restrict__ centers,
                        float* __restrict__ out)
{
    extern __shared__ char smem[];
    const uint32_t smem_base = smem_u32(smem);
    const int tid  = threadIdx.x;
    const int warp = tid >> 5;
    const int lane = tid & 31;
    const int row0 = blockIdx.x * ROWS_PER_BLOCK;

    if (tid == 0) {
        #pragma unroll
        for (int s = 0; s < NSTAGES; s++)
            mbar_init(smem_base + SMEM_MBAR + s * 8, 1);
    }
    __syncthreads();

    // TMA path: all 4 x stages issued up-front by thread 0 (4 x 16KB).
    if (tid == 0) {
        #pragma unroll
        for (int s = 0; s < NSTAGES; s++) {
            const uint32_t mbar = smem_base + SMEM_MBAR + s * 8;
            mbar_expect_tx(mbar, STAGE_BYTES);
            bulk_copy(smem_base + SMEM_X + s * STAGE_BYTES,
                      (const char*)x + (size_t)(row0 + s * STAGE_ROWS) * ROW_BYTES,
                      STAGE_BYTES, mbar);
        }
    }

    // LSU path: warp w owns stage-row w of every stage (global row row0+s*8+w).
    float s_acc = 0.0f;

    #pragma unroll
    for (int s = 0; s < NSTAGES; s++) {
        const int row = row0 + s * STAGE_ROWS + warp;
        int lab = labels[row];
        lab = min(max(lab, 0), C_ROWS - 1);
        const float4* cr = (const float4*)centers + (size_t)lab * 128 + lane;

        // Front-batch the center row (4 LDG.128/lane) BEFORE the TMA wait:
        // gather latency hides behind the bulk-copy completion.
        float4 b0 = cr[0];
        float4 b1 = cr[32];
        float4 b2 = cr[64];
        float4 b3 = cr[96];

        mbar_wait0(smem_base + SMEM_MBAR + s * 8);

        const float4* xs = (const float4*)(smem + SMEM_X + s * STAGE_BYTES
                                           + warp * ROW_BYTES) + lane;
        const float4 a0 = xs[0];
        const float4 a1 = xs[32];
        const float4 a2 = xs[64];
        const float4 a3 = xs[96];

        float dx, dy, dz, dw;
        dx = a0.x - b0.x; dy = a0.y - b0.y; dz = a0.z - b0.z; dw = a0.w - b0.w;
        s_acc += dx*dx + dy*dy + dz*dz + dw*dw;
        dx = a1.x - b1.x; dy = a1.y - b1.y; dz = a1.z - b1.z; dw = a1.w - b1.w;
        s_acc += dx*dx + dy*dy + dz*dz + dw*dw;
        dx = a2.x - b2.x; dy = a2.y - b2.y; dz = a2.z - b2.z; dw = a2.w - b2.w;
        s_acc += dx*dx + dy*dy + dz*dz + dw*dw;
        dx = a3.x - b3.x; dy = a3.y - b3.y; dz = a3.z - b3.z; dw = a3.w - b3.w;
        s_acc += dx*dx + dy*dy + dz*dz + dw*dw;
    }

    // Reduce: warp -> block -> one atomic per block.
    #pragma unroll
    for (int o = 16; o > 0; o >>= 1)
        s_acc += __shfl_xor_sync(0xFFFFFFFFu, s_acc, o);

    __shared__ float warp_sums[THREADS / 32];
    if (lane == 0) warp_sums[warp] = s_acc;
    __syncthreads();

    if (warp == 0) {
        float v = (lane < THREADS / 32) ? warp_sums[lane] : 0.0f;
        #pragma unroll
        for (int o = 4; o > 0; o >>= 1)
            v += __shfl_xor_sync(0xFFFFFFFFu, v, o);
        if (lane == 0)
            atomicAdd(out, v * (1.0f / (float)B_ROWS));
    }
}

extern "C" void kernel_launch(void* const* d_in, const int* in_sizes, int n_in,
                              void* d_out, int out_size)
{
    const float* x       = (const float*)d_in[0];
    const int*   labels  = (const int*)d_in[1];
    const float* centers = (const float*)d_in[2];
    float*       out     = (float*)d_out;

    static int smem_set = 0;
    if (!smem_set) {
        cudaFuncSetAttribute(center_loss_kernel,
                             cudaFuncAttributeMaxDynamicSharedMemorySize, SMEM_TOTAL);
        smem_set = 1;
    }

    cudaMemsetAsync(out, 0, sizeof(float));
    center_loss_kernel<<<BLOCKS, THREADS, SMEM_TOTAL>>>(x, labels, centers, out);
}